// round 2
// baseline (speedup 1.0000x reference)
#include <cuda_runtime.h>
#include <math.h>

#define BB 2
#define PP 8192
#define KK 20
#define NT 64       // threads per block (queries per block)
#define TILE 512    // db points staged in smem per stage
#define BUFN 24     // per-thread candidate buffer depth

// Scratch: transformed db points/normals in SoA (per side), accumulators.
__device__ double g_acc[2];
__device__ __align__(16) float g_x[2][BB * PP];
__device__ __align__(16) float g_y[2][BB * PP];
__device__ __align__(16) float g_z[2][BB * PP];
__device__ __align__(16) float g_nx[2][BB * PP];
__device__ __align__(16) float g_ny[2][BB * PP];
__device__ __align__(16) float g_nz[2][BB * PP];

// ---- f32x2 packed-math helpers (sm_100+) ----
__device__ __forceinline__ unsigned long long f2add(unsigned long long a, unsigned long long b) {
    unsigned long long r; asm("add.rn.f32x2 %0,%1,%2;" : "=l"(r) : "l"(a), "l"(b)); return r;
}
__device__ __forceinline__ unsigned long long f2mul(unsigned long long a, unsigned long long b) {
    unsigned long long r; asm("mul.rn.f32x2 %0,%1,%2;" : "=l"(r) : "l"(a), "l"(b)); return r;
}
__device__ __forceinline__ unsigned long long f2fma(unsigned long long a, unsigned long long b, unsigned long long c) {
    unsigned long long r; asm("fma.rn.f32x2 %0,%1,%2,%3;" : "=l"(r) : "l"(a), "l"(b), "l"(c)); return r;
}
__device__ __forceinline__ unsigned long long fpack2(float lo, float hi) {
    unsigned long long r; asm("mov.b64 %0,{%1,%2};" : "=l"(r) : "f"(lo), "f"(hi)); return r;
}

__global__ void init_kernel() {
    g_acc[0] = 0.0;
    g_acc[1] = 0.0;
}

__global__ void transform_kernel(const float* __restrict__ xyz1, const float* __restrict__ normal1,
                                 const float* __restrict__ xyz2, const float* __restrict__ normal2,
                                 const float* __restrict__ R12, const float* __restrict__ t12,
                                 const float* __restrict__ R21, const float* __restrict__ t21) {
    int i = blockIdx.x * blockDim.x + threadIdx.x;
    if (i >= BB * PP) return;
    int b = i >> 13;

    // side 0 db = R12 @ xyz2 + t12
    {
        const float* R = R12 + b * 9;
        const float* t = t12 + b * 3;
        float x = xyz2[3 * i + 0], y = xyz2[3 * i + 1], z = xyz2[3 * i + 2];
        g_x[0][i] = R[0] * x + R[1] * y + R[2] * z + t[0];
        g_y[0][i] = R[3] * x + R[4] * y + R[5] * z + t[1];
        g_z[0][i] = R[6] * x + R[7] * y + R[8] * z + t[2];
        float nx = normal2[3 * i + 0], ny = normal2[3 * i + 1], nz = normal2[3 * i + 2];
        g_nx[0][i] = R[0] * nx + R[1] * ny + R[2] * nz;
        g_ny[0][i] = R[3] * nx + R[4] * ny + R[5] * nz;
        g_nz[0][i] = R[6] * nx + R[7] * ny + R[8] * nz;
    }
    // side 1 db = R21 @ xyz1 + t21
    {
        const float* R = R21 + b * 9;
        const float* t = t21 + b * 3;
        float x = xyz1[3 * i + 0], y = xyz1[3 * i + 1], z = xyz1[3 * i + 2];
        g_x[1][i] = R[0] * x + R[1] * y + R[2] * z + t[0];
        g_y[1][i] = R[3] * x + R[4] * y + R[5] * z + t[1];
        g_z[1][i] = R[6] * x + R[7] * y + R[8] * z + t[2];
        float nx = normal1[3 * i + 0], ny = normal1[3 * i + 1], nz = normal1[3 * i + 2];
        g_nx[1][i] = R[0] * nx + R[1] * ny + R[2] * nz;
        g_ny[1][i] = R[3] * nx + R[4] * ny + R[5] * nz;
        g_nz[1][i] = R[6] * nx + R[7] * ny + R[8] * nz;
    }
}

// Thread per query; full db scan through smem tiles; buffered-threshold top-20 sieve
// on packed keys (truncated d2 mantissa | 13-bit idx); exact recompute in epilogue.
__global__ __launch_bounds__(NT) void knn_kernel(
    const float* __restrict__ xyz1, const float* __restrict__ hsv1,
    const float* __restrict__ normal1, const float* __restrict__ nres1,
    const float* __restrict__ xyz2, const float* __restrict__ hsv2,
    const float* __restrict__ normal2, const float* __restrict__ nres2,
    const int* __restrict__ npts1, const int* __restrict__ npts2) {
    const int s = blockIdx.y;
    const int tid = threadIdx.x;
    const int qi = blockIdx.x * NT + tid;   // 0 .. BB*PP-1 (b uniform per block)
    const int b = qi >> 13;
    const int p_local = qi & (PP - 1);
    const int boff = b * PP;

    const float* xq  = s ? xyz2 : xyz1;
    const float* hq  = s ? hsv2 : hsv1;
    const float* nq  = s ? normal2 : normal1;
    const float* rq  = s ? nres2 : nres1;
    const float* hdb = s ? hsv1 : hsv2;
    const float* rdb = s ? nres1 : nres2;
    const int lq  = (s ? npts2 : npts1)[b];
    const int ldb = (s ? npts1 : npts2)[b];

    const float* gx  = g_x[s]  + boff;
    const float* gy  = g_y[s]  + boff;
    const float* gz  = g_z[s]  + boff;
    const float* gnx = g_nx[s] + boff;
    const float* gny = g_ny[s] + boff;
    const float* gnz = g_nz[s] + boff;

    const float qx = xq[3 * qi + 0];
    const float qy = xq[3 * qi + 1];
    const float qz = xq[3 * qi + 2];
    const unsigned long long nqx2 = fpack2(-qx, -qx);
    const unsigned long long nqy2 = fpack2(-qy, -qy);
    const unsigned long long nqz2 = fpack2(-qz, -qz);

    float keys[KK];
#pragma unroll
    for (int k = 0; k < KK; k++) keys[k] = 3.0e38f;
    float threshf = 3.0e38f;
    int cnt = 0;

    __shared__ float sx[TILE], sy[TILE], sz[TILE];
    __shared__ unsigned buf[BUFN][NT];

    // Flush: run the insert chain for all buffered candidates (warp-coherent call sites).
    auto flushf = [&]() {
        for (int j2 = 0; j2 < cnt; j2++) {
            float kk = __uint_as_float(buf[j2][tid]);
#pragma unroll
            for (int k = 0; k < KK; k++) {
                float lo = fminf(kk, keys[k]);
                float hi = fmaxf(kk, keys[k]);
                keys[k] = lo;
                kk = hi;
            }
        }
        cnt = 0;
        threshf = keys[KK - 1] * 1.0019f;  // small margin against packed-key truncation
    };

    auto push = [&](float d2v, unsigned j) {
        unsigned key = (__float_as_uint(d2v) & 0xFFFFE000u) | j;
        buf[cnt][tid] = key;
        cnt++;
        if (cnt == BUFN) flushf();  // warm-up overflows are lane-coincident
    };

    const int ntile = (ldb + TILE - 1) / TILE;
    for (int tb = 0; tb < ntile; ++tb) {
        const int base = tb * TILE;
        __syncthreads();
        // Stage TILE db points into smem (float4 copies, patch invalid tail).
        {
            const float4* gx4 = (const float4*)(gx + base);
            const float4* gy4 = (const float4*)(gy + base);
            const float4* gz4 = (const float4*)(gz + base);
#pragma unroll
            for (int c = 0; c < TILE / 4 / NT; c++) {
                int e = c * NT + tid;
                float4 vx = gx4[e];
                float4 vy = gy4[e];
                float4 vz = gz4[e];
                int j0 = base + e * 4;
                if (j0 + 3 >= ldb) {  // invalidating x alone makes d2 huge
                    if (j0 + 0 >= ldb) vx.x = 1e30f;
                    if (j0 + 1 >= ldb) vx.y = 1e30f;
                    if (j0 + 2 >= ldb) vx.z = 1e30f;
                    if (j0 + 3 >= ldb) vx.w = 1e30f;
                }
                ((float4*)sx)[e] = vx;
                ((float4*)sy)[e] = vy;
                ((float4*)sz)[e] = vz;
            }
        }
        __syncthreads();

        const unsigned long long* sxu = (const unsigned long long*)sx;
        const unsigned long long* syu = (const unsigned long long*)sy;
        const unsigned long long* szu = (const unsigned long long*)sz;
#pragma unroll 4
        for (int p = 0; p < TILE / 2; p++) {
            unsigned long long dx2 = f2add(sxu[p], nqx2);
            unsigned long long dy2 = f2add(syu[p], nqy2);
            unsigned long long dz2 = f2add(szu[p], nqz2);
            unsigned long long d2p = f2mul(dz2, dz2);
            d2p = f2fma(dy2, dy2, d2p);
            d2p = f2fma(dx2, dx2, d2p);
            float d0, d1;
            asm("mov.b64 {%0,%1},%2;" : "=f"(d0), "=f"(d1) : "l"(d2p));
            if (fminf(d0, d1) < threshf) {
                unsigned j = (unsigned)(base + 2 * p);
                if (d0 < threshf) push(d0, j);
                if (d1 < threshf) push(d1, j + 1);
            }
        }
        // Per-tile warp-coherent flush keeps buffers shallow.
        flushf();
    }
    flushf();

    // Epilogue: recompute exact terms from recovered indices.
    float sum = 0.f;
    if (p_local < lq) {
        float ell = fmaxf(0.015f * (qz - 10.0f), 0.15f);
        float inv_ls = 1.0f / (ell * ell);
        float hx = hq[3 * qi + 0], hy = hq[3 * qi + 1], hz = hq[3 * qi + 2];
        float nx = nq[3 * qi + 0], ny = nq[3 * qi + 1], nz = nq[3 * qi + 2];
        float rqv = rq[qi];
#pragma unroll
        for (int k = 0; k < KK; k++) {
            int idx = (int)(__float_as_uint(keys[k]) & 0x1FFFu);
            float dx = qx - gx[idx], dy = qy - gy[idx], dz = qz - gz[idx];
            float d2 = fmaf(dx, dx, fmaf(dy, dy, dz * dz));
            int g = boff + idx;
            float chx = hx - hdb[3 * g + 0];
            float chy = hy - hdb[3 * g + 1];
            float chz = hz - hdb[3 * g + 2];
            float cd = sqrtf(fmaf(chx, chx, fmaf(chy, chy, chz * chz)) + 1e-12f);
            float ndot = fmaf(nx, gnx[idx], fmaf(ny, gny[idx], nz * gnz[idx]));
            float rk = rdb[g];
            float alpha = 0.2f / (0.1f + rqv + rk);
            float nk = fmaxf(ndot * alpha, 0.0f);
            float e = expf(-(d2 * inv_ls + cd * 5.0f));
            sum += e * nk;
        }
    }

    // Block reduce + one double atomic per block.
    __shared__ float red[NT];
    red[tid] = sum;
    __syncthreads();
#pragma unroll
    for (int st = NT / 2; st > 0; st >>= 1) {
        if (tid < st) red[tid] += red[tid + st];
        __syncthreads();
    }
    if (tid == 0) atomicAdd(&g_acc[s], (double)red[0]);
}

__global__ void finalize_kernel(const int* __restrict__ npts1, const int* __restrict__ npts2,
                                float* __restrict__ out) {
    double s1 = 0.0, s2 = 0.0;
    for (int b = 0; b < BB; b++) {
        s1 += (double)npts1[b];
        s2 += (double)npts2[b];
    }
    double k1 = g_acc[0] / (s1 * (double)KK);
    double k2 = g_acc[1] / (s2 * (double)KK);
    out[0] = (float)(0.5 * (k1 + k2));
}

extern "C" void kernel_launch(void* const* d_in, const int* in_sizes, int n_in,
                              void* d_out, int out_size) {
    const float* xyz1    = (const float*)d_in[0];
    const float* xyz2    = (const float*)d_in[1];
    const float* hsv1    = (const float*)d_in[2];
    const float* hsv2    = (const float*)d_in[3];
    const float* normal1 = (const float*)d_in[4];
    const float* normal2 = (const float*)d_in[5];
    const float* nres1   = (const float*)d_in[6];
    const float* nres2   = (const float*)d_in[7];
    const float* R12     = (const float*)d_in[8];
    const float* t12     = (const float*)d_in[9];
    const float* R21     = (const float*)d_in[10];
    const float* t21     = (const float*)d_in[11];
    const int*   npts1   = (const int*)d_in[12];
    const int*   npts2   = (const int*)d_in[13];
    float* out = (float*)d_out;

    init_kernel<<<1, 1>>>();
    transform_kernel<<<(BB * PP + 255) / 256, 256>>>(xyz1, normal1, xyz2, normal2,
                                                     R12, t12, R21, t21);
    dim3 grid(BB * PP / NT, 2);
    knn_kernel<<<grid, NT>>>(xyz1, hsv1, normal1, nres1,
                             xyz2, hsv2, normal2, nres2, npts1, npts2);
    finalize_kernel<<<1, 1>>>(npts1, npts2, out);
}

// round 4
// speedup vs baseline: 1.3107x; 1.3107x over previous
#include <cuda_runtime.h>
#include <math.h>

#define BB 2
#define PP 8192
#define KK 20
#define NT 128
#define TILE 256

__device__ double g_acc[2];
__device__ unsigned int g_cnt;

__global__ void init_kernel() {
    g_acc[0] = 0.0;
    g_acc[1] = 0.0;
    g_cnt = 0u;
}

// One thread per query; db staged+rotated through smem tiles; top-20 kept as 4
// independent sorted chains of 5 packed keys (d2 high-mantissa | 13-bit idx).
// Last block computes the final scalar.
__global__ __launch_bounds__(NT) void knn_kernel(
    const float* __restrict__ xyz1, const float* __restrict__ hsv1,
    const float* __restrict__ normal1, const float* __restrict__ nres1,
    const float* __restrict__ xyz2, const float* __restrict__ hsv2,
    const float* __restrict__ normal2, const float* __restrict__ nres2,
    const float* __restrict__ R12, const float* __restrict__ t12,
    const float* __restrict__ R21, const float* __restrict__ t21,
    const int* __restrict__ npts1, const int* __restrict__ npts2,
    float* __restrict__ out)
{
    const int s = blockIdx.y;
    const int tid = threadIdx.x;
    const int qi = blockIdx.x * NT + tid;      // batch uniform per block
    const int b = qi >> 13;
    const int p_local = qi & (PP - 1);
    const int boff = b * PP;

    const float* xq   = s ? xyz2 : xyz1;
    const float* hq   = s ? hsv2 : hsv1;
    const float* nq   = s ? normal2 : normal1;
    const float* rq   = s ? nres2 : nres1;
    const float* xdbr = s ? xyz1 : xyz2;       // raw (untransformed) db points
    const float* ndbr = s ? normal1 : normal2;
    const float* hdb  = s ? hsv1 : hsv2;
    const float* rdb  = s ? nres1 : nres2;
    const float* Rm   = (s ? R21 : R12) + b * 9;
    const float* tv   = (s ? t21 : t12) + b * 3;
    const int lq  = (s ? npts2 : npts1)[b];
    const int ldb = (s ? npts1 : npts2)[b];

    const float R0 = Rm[0], R1 = Rm[1], R2 = Rm[2];
    const float R3 = Rm[3], R4 = Rm[4], R5 = Rm[5];
    const float R6 = Rm[6], R7 = Rm[7], R8 = Rm[8];
    const float t0 = tv[0], t1 = tv[1], t2 = tv[2];

    const float qx = xq[3 * qi + 0];
    const float qy = xq[3 * qi + 1];
    const float qz = xq[3 * qi + 2];

    float keys[KK];                 // 4 sorted-ascending chains: [0..4][5..9][10..14][15..19]
#pragma unroll
    for (int k = 0; k < KK; k++) keys[k] = 3.0e38f;
    float thresh = 3.0e38f;         // max of the 4 chain tails = global 20th best

    __shared__ float4 sm[TILE];

    const int ntile = (ldb + TILE - 1) / TILE;
    for (int tb = 0; tb < ntile; ++tb) {
        const int base = tb * TILE;
        __syncthreads();
        // Stage TILE db points: load raw, rotate into query frame, write float4.
#pragma unroll
        for (int c = 0; c < TILE / NT; c++) {
            int e = c * NT + tid;
            int j = base + e;
            float4 v;
            if (j < ldb) {
                int g3 = 3 * (boff + j);
                float px = xdbr[g3 + 0], py = xdbr[g3 + 1], pz = xdbr[g3 + 2];
                v.x = fmaf(R0, px, fmaf(R1, py, fmaf(R2, pz, t0)));
                v.y = fmaf(R3, px, fmaf(R4, py, fmaf(R5, pz, t1)));
                v.z = fmaf(R6, px, fmaf(R7, py, fmaf(R8, pz, t2)));
                v.w = 0.f;
            } else {
                v = make_float4(1e30f, 1e30f, 1e30f, 0.f);  // d2 -> inf, never accepted
            }
            sm[e] = v;
        }
        __syncthreads();

        for (int jj = 0; jj < TILE; jj += 8) {
            float d2a[8];
#pragma unroll
            for (int u = 0; u < 8; u++) {
                float4 pv = sm[jj + u];
                float dx = qx - pv.x, dy = qy - pv.y, dz = qz - pv.z;
                d2a[u] = fmaf(dx, dx, fmaf(dy, dy, dz * dz));
            }
            float m = fminf(fminf(fminf(d2a[0], d2a[1]), fminf(d2a[2], d2a[3])),
                            fminf(fminf(d2a[4], d2a[5]), fminf(d2a[6], d2a[7])));
            if (m < thresh) {
#pragma unroll
                for (int u = 0; u < 8; u++) {
                    if (d2a[u] < thresh) {
                        float x = __uint_as_float(
                            (__float_as_uint(d2a[u]) & 0xFFFFE000u) | (unsigned)(base + jj + u));
                        // chain with max tail receives the candidate (evicts global max)
                        float tt0 = keys[4], tt1 = keys[9], tt2 = keys[14], tt3 = keys[19];
                        int sel = 0; float bestv = tt0;
                        if (tt1 > bestv) { bestv = tt1; sel = 1; }
                        if (tt2 > bestv) { bestv = tt2; sel = 2; }
                        if (tt3 > bestv) { bestv = tt3; sel = 3; }
                        float x0 = (sel == 0) ? x : 3.3e38f;   // +INF-ish insert = no-op
                        float x1 = (sel == 1) ? x : 3.3e38f;
                        float x2 = (sel == 2) ? x : 3.3e38f;
                        float x3 = (sel == 3) ? x : 3.3e38f;
#pragma unroll
                        for (int k = 0; k < 5; k++) {
                            float lo = fminf(x0, keys[k]); x0 = fmaxf(x0, keys[k]); keys[k] = lo;
                        }
#pragma unroll
                        for (int k = 5; k < 10; k++) {
                            float lo = fminf(x1, keys[k]); x1 = fmaxf(x1, keys[k]); keys[k] = lo;
                        }
#pragma unroll
                        for (int k = 10; k < 15; k++) {
                            float lo = fminf(x2, keys[k]); x2 = fmaxf(x2, keys[k]); keys[k] = lo;
                        }
#pragma unroll
                        for (int k = 15; k < 20; k++) {
                            float lo = fminf(x3, keys[k]); x3 = fmaxf(x3, keys[k]); keys[k] = lo;
                        }
                        thresh = fmaxf(fmaxf(keys[4], keys[9]), fmaxf(keys[14], keys[19]));
                    }
                }
            }
        }
    }

    // Epilogue: recompute exact terms for the 20 winners from raw inputs + R,t.
    float sum = 0.f;
    if (p_local < lq) {
        float ell = fmaxf(0.015f * (qz - 10.0f), 0.15f);
        float inv_ls = 1.0f / (ell * ell);
        float hx = hq[3 * qi + 0], hy = hq[3 * qi + 1], hz = hq[3 * qi + 2];
        float nx = nq[3 * qi + 0], ny = nq[3 * qi + 1], nz = nq[3 * qi + 2];
        float rqv = rq[qi];
#pragma unroll
        for (int k = 0; k < KK; k++) {
            int idx = (int)(__float_as_uint(keys[k]) & 0x1FFFu);
            int g3 = 3 * (boff + idx);
            float px = xdbr[g3 + 0], py = xdbr[g3 + 1], pz = xdbr[g3 + 2];
            float wx = fmaf(R0, px, fmaf(R1, py, fmaf(R2, pz, t0)));
            float wy = fmaf(R3, px, fmaf(R4, py, fmaf(R5, pz, t1)));
            float wz = fmaf(R6, px, fmaf(R7, py, fmaf(R8, pz, t2)));
            float dx = qx - wx, dy = qy - wy, dz = qz - wz;
            float d2 = fmaf(dx, dx, fmaf(dy, dy, dz * dz));
            float mx = ndbr[g3 + 0], my = ndbr[g3 + 1], mz = ndbr[g3 + 2];
            float nwx = fmaf(R0, mx, fmaf(R1, my, R2 * mz));
            float nwy = fmaf(R3, mx, fmaf(R4, my, R5 * mz));
            float nwz = fmaf(R6, mx, fmaf(R7, my, R8 * mz));
            float ndot = fmaf(nx, nwx, fmaf(ny, nwy, nz * nwz));
            float chx = hx - hdb[g3 + 0];
            float chy = hy - hdb[g3 + 1];
            float chz = hz - hdb[g3 + 2];
            float cd = sqrtf(fmaf(chx, chx, fmaf(chy, chy, chz * chz)) + 1e-12f);
            float rk = rdb[boff + idx];
            float alpha = 0.2f / (0.1f + rqv + rk);
            float nk = fmaxf(ndot * alpha, 0.0f);
            sum += __expf(-(d2 * inv_ls + cd * 5.0f)) * nk;
        }
    }

    // Warp reduce + block reduce + one double atomic per block.
#pragma unroll
    for (int o = 16; o > 0; o >>= 1) sum += __shfl_down_sync(0xffffffffu, sum, o);
    __shared__ float wsum[NT / 32];
    if ((tid & 31) == 0) wsum[tid >> 5] = sum;
    __syncthreads();
    if (tid == 0) {
        float bs = 0.f;
#pragma unroll
        for (int w = 0; w < NT / 32; w++) bs += wsum[w];
        atomicAdd(&g_acc[s], (double)bs);
        __threadfence();
        unsigned done = atomicAdd(&g_cnt, 1u);
        if (done == (unsigned)(gridDim.x * gridDim.y) - 1u) {
            double s1 = (double)npts1[0] + (double)npts1[1];
            double s2 = (double)npts2[0] + (double)npts2[1];
            double k1 = g_acc[0] / (s1 * (double)KK);
            double k2 = g_acc[1] / (s2 * (double)KK);
            out[0] = (float)(0.5 * (k1 + k2));
        }
    }
}

extern "C" void kernel_launch(void* const* d_in, const int* in_sizes, int n_in,
                              void* d_out, int out_size) {
    const float* xyz1    = (const float*)d_in[0];
    const float* xyz2    = (const float*)d_in[1];
    const float* hsv1    = (const float*)d_in[2];
    const float* hsv2    = (const float*)d_in[3];
    const float* normal1 = (const float*)d_in[4];
    const float* normal2 = (const float*)d_in[5];
    const float* nres1   = (const float*)d_in[6];
    const float* nres2   = (const float*)d_in[7];
    const float* R12     = (const float*)d_in[8];
    const float* t12     = (const float*)d_in[9];
    const float* R21     = (const float*)d_in[10];
    const float* t21     = (const float*)d_in[11];
    const int*   npts1   = (const int*)d_in[12];
    const int*   npts2   = (const int*)d_in[13];
    float* out = (float*)d_out;

    init_kernel<<<1, 1>>>();
    dim3 grid(BB * PP / NT, 2);
    knn_kernel<<<grid, NT>>>(xyz1, hsv1, normal1, nres1,
                             xyz2, hsv2, normal2, nres2,
                             R12, t12, R21, t21, npts1, npts2, out);
}